// round 16
// baseline (speedup 1.0000x reference)
#include <cuda_runtime.h>
#include <cuda_bf16.h>
#include <cstdint>
#include <cstddef>

#define LOG2E_F 1.4426950408889634f
#define LN2_F   0.6931471805599453f

__device__ __forceinline__ float ex2f_(float x) { float y; asm("ex2.approx.ftz.f32 %0, %1;" : "=f"(y) : "f"(x)); return y; }
__device__ __forceinline__ float lg2f_(float x) { float y; asm("lg2.approx.f32 %0, %1;" : "=f"(y) : "f"(x)); return y; }

__device__ __forceinline__ unsigned pk2h_(__nv_bfloat16 lo, __nv_bfloat16 hi) {
    __nv_bfloat162 t; t.x = lo; t.y = hi;
    return *reinterpret_cast<unsigned*>(&t);
}
__device__ __forceinline__ unsigned pkf2_(float lo, float hi) {
    return pk2h_(__float2bfloat16_rn(lo), __float2bfloat16_rn(hi));
}
__device__ __forceinline__ void mma_bf16_(float* c,
                                          unsigned a0, unsigned a1, unsigned a2, unsigned a3,
                                          unsigned b0, unsigned b1) {
    asm("mma.sync.aligned.m16n8k16.row.col.f32.bf16.bf16.f32 "
        "{%0,%1,%2,%3}, {%4,%5,%6,%7}, {%8,%9}, {%0,%1,%2,%3};"
        : "+f"(c[0]), "+f"(c[1]), "+f"(c[2]), "+f"(c[3])
        : "r"(a0), "r"(a1), "r"(a2), "r"(a3), "r"(b0), "r"(b1));
}
__device__ __forceinline__ void ldsm4_(unsigned& a0, unsigned& a1, unsigned& a2, unsigned& a3,
                                       unsigned addr) {
    asm volatile("ldmatrix.sync.aligned.m8n8.x4.shared.b16 {%0,%1,%2,%3}, [%4];"
                 : "=r"(a0), "=r"(a1), "=r"(a2), "=r"(a3) : "r"(addr));
}

// 16 batches per CTA on tensor cores, v3 (warp-specialized):
//  - 384 threads. Warps 0-7 = CONSUMERS: warp w owns 16 output columns;
//    per step 8 ldmatrix.x4 + 16 HMMA in TWO depth-4 accumulator chains
//    (kk 0-3 -> cA, kk 4-7 -> cB, merged by FADD) + epilogue. Psm factors
//    are loaded BEFORE the MMA loop (ready since the last barrier).
//  - Warps 8-11 = PRODUCERS: stage p(t+1)=exp(obs[t+1]) into Psm and run
//    the obs prefetch rings. All MUFU latency and staging instructions are
//    OFF the consumer critical chain, overlapping the MMA work.
//  - E stored bf16 hi-only in consumer registers (R14-validated, ~4e-5).
//  - Renorm every 8 steps from state-0 bf16 exponent (exact power of 2,
//    folded into the epilogue); per-batch L in smem.
//  - ONE __syncthreads per step covers both roles.
__global__ __launch_bounds__(384, 1)
void crf_mma_kernel(const float* __restrict__ obs,
                    const float* __restrict__ logA,
                    float* __restrict__ out,
                    int T, int B)
{
    constexpr int S  = 128;
    constexpr int SB = 16;    // batches per CTA
    constexpr int VR = 136;   // V row stride in bf16 units (272B = 17*16B)
    constexpr int PR = 132;   // P row stride in floats (528B, bank-skewed)

    __shared__ unsigned short Vsm[2][SB * VR];  // v, bf16
    __shared__ float          Psm[2][SB * PR];  // exp(obs[t]), f32
    __shared__ int            Lacc[SB];
    __shared__ float          psum[SB][16];

    const int tid = threadIdx.x;
    const int w   = tid >> 5;
    const int l   = tid & 31;
    const int g   = l >> 2;
    const int tg  = l & 3;
    const int b0  = SB * (int)blockIdx.x;
    const bool consumer = (tid < 256);

    // consumer v0-init / finalize mapping: batch sb_c, 8 cols at sj_c
    const int sb_c = (tid & 255) >> 4;
    const int sj_c = (tid & 15) * 8;
    const int bc   = (b0 + sb_c < B) ? (b0 + sb_c) : (B - 1);
    const float* obs_c = obs + (size_t)bc * (size_t)T * S;

    // producer mapping: ptid in [0,128): batch sb_p, 16 cols at sj_p
    const int ptid = tid - 256;
    const int sb_p = (ptid >= 0) ? (ptid >> 3) : 0;
    const int sj_p = (ptid >= 0) ? ((ptid & 7) * 16) : 0;
    const int bp   = (b0 + sb_p < B) ? (b0 + sb_p) : (B - 1);
    const float* obs_p = obs + (size_t)bp * (size_t)T * S;

    // ---- E fragments (consumers only): bf16 hi, col-major k16n8 ----
    unsigned bh0[8][2], bh1[8][2];
    if (consumer) {
#pragma unroll
        for (int kk = 0; kk < 8; ++kk) {
#pragma unroll
            for (int nn = 0; nn < 2; ++nn) {
                const int j  = w * 16 + nn * 8 + g;
                const int i0 = kk * 16 + 2 * tg;
                bh0[kk][nn] = pkf2_(ex2f_(logA[(size_t)(i0    ) * S + j] * LOG2E_F),
                                    ex2f_(logA[(size_t)(i0 + 1) * S + j] * LOG2E_F));
                bh1[kk][nn] = pkf2_(ex2f_(logA[(size_t)(i0 + 8) * S + j] * LOG2E_F),
                                    ex2f_(logA[(size_t)(i0 + 9) * S + j] * LOG2E_F));
            }
        }
    }
    if (tid < SB) Lacc[tid] = 0;

    // ldmatrix lane base offsets
    const int m_ = l >> 3, r_ = l & 7;
    const int lrow = r_ + ((m_ & 1) << 3);
    const int lcol = (m_ >> 1) << 3;
    unsigned vbase[2];
    vbase[0] = (unsigned)__cvta_generic_to_shared(&Vsm[0][0]) + (lrow * VR + lcol) * 2;
    vbase[1] = (unsigned)__cvta_generic_to_shared(&Vsm[1][0]) + (lrow * VR + lcol) * 2;

    // producer obs register rings (16 floats each): rng0 even t', rng1 odd
    float rng0[16], rng1[16];

    if (consumer) {
        // ---- v(0) = exp(obs[0]) into Vsm[0] ----
        const float4* src = reinterpret_cast<const float4*>(obs_c + sj_c);
        float vv[8];
#pragma unroll
        for (int q = 0; q < 2; ++q) {
            const float4 f = src[q];
            vv[4 * q + 0] = ex2f_(f.x * LOG2E_F);
            vv[4 * q + 1] = ex2f_(f.y * LOG2E_F);
            vv[4 * q + 2] = ex2f_(f.z * LOG2E_F);
            vv[4 * q + 3] = ex2f_(f.w * LOG2E_F);
        }
#pragma unroll
        for (int m = 0; m < 4; ++m)
            *reinterpret_cast<unsigned*>(&Vsm[0][sb_c * VR + sj_c + 2 * m]) =
                pkf2_(vv[2 * m], vv[2 * m + 1]);
    } else {
        // ---- stage p(1) into Psm[1]; init rings with obs[2], obs[3] ----
        if (T > 1) {
            const float4* src = reinterpret_cast<const float4*>(obs_p + (size_t)1 * S + sj_p);
            float* dst = &Psm[1][sb_p * PR + sj_p];
#pragma unroll
            for (int q = 0; q < 4; ++q) {
                const float4 f = src[q];
                float4 p;
                p.x = ex2f_(f.x * LOG2E_F); p.y = ex2f_(f.y * LOG2E_F);
                p.z = ex2f_(f.z * LOG2E_F); p.w = ex2f_(f.w * LOG2E_F);
                reinterpret_cast<float4*>(dst)[q] = p;
            }
        }
        const int t2 = (2 < T) ? 2 : (T - 1);
        const int t3 = (3 < T) ? 3 : (T - 1);
        const float4* s2 = reinterpret_cast<const float4*>(obs_p + (size_t)t2 * S + sj_p);
        const float4* s3 = reinterpret_cast<const float4*>(obs_p + (size_t)t3 * S + sj_p);
#pragma unroll
        for (int q = 0; q < 4; ++q) {
            const float4 a = s2[q], c = s3[q];
            rng0[4 * q] = a.x; rng0[4 * q + 1] = a.y; rng0[4 * q + 2] = a.z; rng0[4 * q + 3] = a.w;
            rng1[4 * q] = c.x; rng1[4 * q + 1] = c.y; rng1[4 * q + 2] = c.z; rng1[4 * q + 3] = c.w;
        }
    }
    __syncthreads();

#define CRF_STEP(T_CUR, RNG)                                                      \
    {                                                                              \
        const int t_ = (T_CUR);                                                    \
        const int cb_ = (t_ - 1) & 1, nb_ = t_ & 1;                                \
        if (consumer) {                                                            \
            const bool fold_ = (t_ & 7) == 1;                                      \
            /* observation factors, ready since last barrier */                    \
            float2 pg_[2], pg8_[2];                                                \
            _Pragma("unroll")                                                      \
            for (int nn = 0; nn < 2; ++nn) {                                       \
                const int j0 = w * 16 + nn * 8 + 2 * tg;                           \
                pg_[nn]  = *reinterpret_cast<const float2*>(&Psm[nb_][ g      * PR + j0]); \
                pg8_[nn] = *reinterpret_cast<const float2*>(&Psm[nb_][(g + 8) * PR + j0]); \
            }                                                                      \
            if (fold_) {                                                           \
                const int eg  = (Vsm[cb_][ g      * VR] >> 7) & 0xFF;              \
                const int eg8 = (Vsm[cb_][(g + 8) * VR] >> 7) & 0xFF;              \
                const float scg  = __int_as_float((254 - eg ) << 23);              \
                const float scg8 = __int_as_float((254 - eg8) << 23);              \
                _Pragma("unroll")                                                  \
                for (int nn = 0; nn < 2; ++nn) {                                   \
                    pg_[nn].x *= scg;  pg_[nn].y *= scg;                           \
                    pg8_[nn].x *= scg8; pg8_[nn].y *= scg8;                        \
                }                                                                  \
                if (w == 0 && tg == 0) { Lacc[g] += eg - 127; Lacc[g + 8] += eg8 - 127; } \
            }                                                                      \
            /* two depth-4 accumulator chains per nn */                            \
            float cA_[2][4], cB_[2][4];                                            \
            _Pragma("unroll")                                                      \
            for (int nn = 0; nn < 2; ++nn)                                         \
                _Pragma("unroll")                                                  \
                for (int r = 0; r < 4; ++r) { cA_[nn][r] = 0.f; cB_[nn][r] = 0.f; }\
            _Pragma("unroll")                                                      \
            for (int kk = 0; kk < 4; ++kk) {                                       \
                unsigned a0, a1, a2, a3, e0, e1, e2, e3;                           \
                ldsm4_(a0, a1, a2, a3, vbase[cb_] + kk * 32);                      \
                ldsm4_(e0, e1, e2, e3, vbase[cb_] + (kk + 4) * 32);                \
                mma_bf16_(cA_[0], a0, a1, a2, a3, bh0[kk][0], bh1[kk][0]);         \
                mma_bf16_(cB_[0], e0, e1, e2, e3, bh0[kk + 4][0], bh1[kk + 4][0]); \
                mma_bf16_(cA_[1], a0, a1, a2, a3, bh0[kk][1], bh1[kk][1]);         \
                mma_bf16_(cB_[1], e0, e1, e2, e3, bh0[kk + 4][1], bh1[kk + 4][1]); \
            }                                                                      \
            _Pragma("unroll")                                                      \
            for (int nn = 0; nn < 2; ++nn) {                                       \
                const int j0 = w * 16 + nn * 8 + 2 * tg;                           \
                const float f0 = (cA_[nn][0] + cB_[nn][0]) * pg_[nn].x;            \
                const float f1 = (cA_[nn][1] + cB_[nn][1]) * pg_[nn].y;            \
                const float f2 = (cA_[nn][2] + cB_[nn][2]) * pg8_[nn].x;           \
                const float f3 = (cA_[nn][3] + cB_[nn][3]) * pg8_[nn].y;           \
                *reinterpret_cast<unsigned*>(&Vsm[nb_][ g      * VR + j0]) = pkf2_(f0, f1); \
                *reinterpret_cast<unsigned*>(&Vsm[nb_][(g + 8) * VR + j0]) = pkf2_(f2, f3); \
            }                                                                      \
        } else {                                                                   \
            /* producers: stage p(t+1); refill ring with obs[t+3] */               \
            if (t_ + 1 < T) {                                                      \
                float* dst = &Psm[(t_ + 1) & 1][sb_p * PR + sj_p];                 \
                _Pragma("unroll")                                                  \
                for (int q = 0; q < 4; ++q) {                                      \
                    float4 p;                                                      \
                    p.x = ex2f_((RNG)[4 * q + 0] * LOG2E_F);                       \
                    p.y = ex2f_((RNG)[4 * q + 1] * LOG2E_F);                       \
                    p.z = ex2f_((RNG)[4 * q + 2] * LOG2E_F);                       \
                    p.w = ex2f_((RNG)[4 * q + 3] * LOG2E_F);                       \
                    reinterpret_cast<float4*>(dst)[q] = p;                         \
                }                                                                  \
            }                                                                      \
            if (t_ + 3 < T) {                                                      \
                const float4* src = reinterpret_cast<const float4*>(obs_p + (size_t)(t_ + 3) * S + sj_p); \
                _Pragma("unroll")                                                  \
                for (int q = 0; q < 4; ++q) {                                      \
                    const float4 f = src[q];                                       \
                    (RNG)[4 * q + 0] = f.x; (RNG)[4 * q + 1] = f.y;                \
                    (RNG)[4 * q + 2] = f.z; (RNG)[4 * q + 3] = f.w;                \
                }                                                                  \
            }                                                                      \
        }                                                                          \
        __syncthreads();                                                           \
    }

    int t = 1;
    for (; t + 1 < T; t += 2) {
        CRF_STEP(t,     rng0)
        CRF_STEP(t + 1, rng1)
    }
    if (t < T) CRF_STEP(t, rng0)
#undef CRF_STEP

    // ---- finalize: out[b] = -ln2 * (log2(sum_j v[b][j]) + L[b]) ----
    const int fb = (T - 1) & 1;
    if (consumer) {
        float s8 = 0.f;
#pragma unroll
        for (int m = 0; m < 8; ++m)
            s8 += __bfloat162float(
                *reinterpret_cast<const __nv_bfloat16*>(&Vsm[fb][sb_c * VR + sj_c + m]));
        psum[sb_c][tid & 15] = s8;
    }
    __syncthreads();
    if (tid < SB && b0 + tid < B) {
        float s = 0.f;
#pragma unroll
        for (int k = 0; k < 16; ++k) s += psum[tid][k];
        out[b0 + tid] = -LN2_F * (lg2f_(s) + (float)Lacc[tid]);
    }
}

extern "C" void kernel_launch(void* const* d_in, const int* in_sizes, int n_in,
                              void* d_out, int out_size)
{
    const float* obs  = (const float*)d_in[0];   // [B, T, S] f32
    const float* logA = (const float*)d_in[1];   // [S, S]   f32
    float* out = (float*)d_out;                  // [B]      f32

    const int B = out_size;
    const int S = 128;
    const int T = in_sizes[0] / (B * S);

    const int grid = (B + 15) / 16;
    crf_mma_kernel<<<grid, 384>>>(obs, logA, out, T, B);
}

// round 17
// speedup vs baseline: 1.0118x; 1.0118x over previous
#include <cuda_runtime.h>
#include <cuda_bf16.h>
#include <cstdint>
#include <cstddef>

#define LOG2E_F 1.4426950408889634f
#define LN2_F   0.6931471805599453f

__device__ __forceinline__ float ex2f_(float x) { float y; asm("ex2.approx.ftz.f32 %0, %1;" : "=f"(y) : "f"(x)); return y; }
__device__ __forceinline__ float lg2f_(float x) { float y; asm("lg2.approx.f32 %0, %1;" : "=f"(y) : "f"(x)); return y; }

__device__ __forceinline__ unsigned pk2h_(__nv_bfloat16 lo, __nv_bfloat16 hi) {
    __nv_bfloat162 t; t.x = lo; t.y = hi;
    return *reinterpret_cast<unsigned*>(&t);
}
__device__ __forceinline__ unsigned pkf2_(float lo, float hi) {
    return pk2h_(__float2bfloat16_rn(lo), __float2bfloat16_rn(hi));
}
__device__ __forceinline__ void mma_bf16_(float* c,
                                          unsigned a0, unsigned a1, unsigned a2, unsigned a3,
                                          unsigned b0, unsigned b1) {
    asm("mma.sync.aligned.m16n8k16.row.col.f32.bf16.bf16.f32 "
        "{%0,%1,%2,%3}, {%4,%5,%6,%7}, {%8,%9}, {%0,%1,%2,%3};"
        : "+f"(c[0]), "+f"(c[1]), "+f"(c[2]), "+f"(c[3])
        : "r"(a0), "r"(a1), "r"(a2), "r"(a3), "r"(b0), "r"(b1));
}
__device__ __forceinline__ void ldsm4_(unsigned& a0, unsigned& a1, unsigned& a2, unsigned& a3,
                                       unsigned addr) {
    asm volatile("ldmatrix.sync.aligned.m8n8.x4.shared.b16 {%0,%1,%2,%3}, [%4];"
                 : "=r"(a0), "=r"(a1), "=r"(a2), "=r"(a3) : "r"(addr));
}

// 16 batches per CTA on tensor cores, v3 (warp-specialized):
//  - 384 threads. Warps 0-7 = CONSUMERS: warp w owns 16 output columns;
//    per step 8 ldmatrix.x4 + 16 HMMA in TWO depth-4 accumulator chains
//    (kk 0-3 -> cA, kk 4-7 -> cB, merged by FADD) + epilogue. Psm factors
//    are loaded BEFORE the MMA loop (ready since the last barrier).
//  - Warps 8-11 = PRODUCERS: stage p(t+1)=exp(obs[t+1]) into Psm and run
//    the obs prefetch rings. All MUFU latency and staging instructions are
//    OFF the consumer critical chain, overlapping the MMA work.
//  - E stored bf16 hi-only in consumer registers (R14-validated, ~4e-5).
//  - Renorm every 8 steps from state-0 bf16 exponent (exact power of 2,
//    folded into the epilogue); per-batch L in smem.
//  - ONE __syncthreads per step covers both roles.
__global__ __launch_bounds__(384, 1)
void crf_mma_kernel(const float* __restrict__ obs,
                    const float* __restrict__ logA,
                    float* __restrict__ out,
                    int T, int B)
{
    constexpr int S  = 128;
    constexpr int SB = 16;    // batches per CTA
    constexpr int VR = 136;   // V row stride in bf16 units (272B = 17*16B)
    constexpr int PR = 132;   // P row stride in floats (528B, bank-skewed)

    __shared__ unsigned short Vsm[2][SB * VR];  // v, bf16
    __shared__ float          Psm[2][SB * PR];  // exp(obs[t]), f32
    __shared__ int            Lacc[SB];
    __shared__ float          psum[SB][16];

    const int tid = threadIdx.x;
    const int w   = tid >> 5;
    const int l   = tid & 31;
    const int g   = l >> 2;
    const int tg  = l & 3;
    const int b0  = SB * (int)blockIdx.x;
    const bool consumer = (tid < 256);

    // consumer v0-init / finalize mapping: batch sb_c, 8 cols at sj_c
    const int sb_c = (tid & 255) >> 4;
    const int sj_c = (tid & 15) * 8;
    const int bc   = (b0 + sb_c < B) ? (b0 + sb_c) : (B - 1);
    const float* obs_c = obs + (size_t)bc * (size_t)T * S;

    // producer mapping: ptid in [0,128): batch sb_p, 16 cols at sj_p
    const int ptid = tid - 256;
    const int sb_p = (ptid >= 0) ? (ptid >> 3) : 0;
    const int sj_p = (ptid >= 0) ? ((ptid & 7) * 16) : 0;
    const int bp   = (b0 + sb_p < B) ? (b0 + sb_p) : (B - 1);
    const float* obs_p = obs + (size_t)bp * (size_t)T * S;

    // ---- E fragments (consumers only): bf16 hi, col-major k16n8 ----
    unsigned bh0[8][2], bh1[8][2];
    if (consumer) {
#pragma unroll
        for (int kk = 0; kk < 8; ++kk) {
#pragma unroll
            for (int nn = 0; nn < 2; ++nn) {
                const int j  = w * 16 + nn * 8 + g;
                const int i0 = kk * 16 + 2 * tg;
                bh0[kk][nn] = pkf2_(ex2f_(logA[(size_t)(i0    ) * S + j] * LOG2E_F),
                                    ex2f_(logA[(size_t)(i0 + 1) * S + j] * LOG2E_F));
                bh1[kk][nn] = pkf2_(ex2f_(logA[(size_t)(i0 + 8) * S + j] * LOG2E_F),
                                    ex2f_(logA[(size_t)(i0 + 9) * S + j] * LOG2E_F));
            }
        }
    }
    if (tid < SB) Lacc[tid] = 0;

    // ldmatrix lane base offsets
    const int m_ = l >> 3, r_ = l & 7;
    const int lrow = r_ + ((m_ & 1) << 3);
    const int lcol = (m_ >> 1) << 3;
    unsigned vbase[2];
    vbase[0] = (unsigned)__cvta_generic_to_shared(&Vsm[0][0]) + (lrow * VR + lcol) * 2;
    vbase[1] = (unsigned)__cvta_generic_to_shared(&Vsm[1][0]) + (lrow * VR + lcol) * 2;

    // producer obs register rings (16 floats each): rng0 even t', rng1 odd
    float rng0[16], rng1[16];

    if (consumer) {
        // ---- v(0) = exp(obs[0]) into Vsm[0] ----
        const float4* src = reinterpret_cast<const float4*>(obs_c + sj_c);
        float vv[8];
#pragma unroll
        for (int q = 0; q < 2; ++q) {
            const float4 f = src[q];
            vv[4 * q + 0] = ex2f_(f.x * LOG2E_F);
            vv[4 * q + 1] = ex2f_(f.y * LOG2E_F);
            vv[4 * q + 2] = ex2f_(f.z * LOG2E_F);
            vv[4 * q + 3] = ex2f_(f.w * LOG2E_F);
        }
#pragma unroll
        for (int m = 0; m < 4; ++m)
            *reinterpret_cast<unsigned*>(&Vsm[0][sb_c * VR + sj_c + 2 * m]) =
                pkf2_(vv[2 * m], vv[2 * m + 1]);
    } else {
        // ---- stage p(1) into Psm[1]; init rings with obs[2], obs[3] ----
        if (T > 1) {
            const float4* src = reinterpret_cast<const float4*>(obs_p + (size_t)1 * S + sj_p);
            float* dst = &Psm[1][sb_p * PR + sj_p];
#pragma unroll
            for (int q = 0; q < 4; ++q) {
                const float4 f = src[q];
                float4 p;
                p.x = ex2f_(f.x * LOG2E_F); p.y = ex2f_(f.y * LOG2E_F);
                p.z = ex2f_(f.z * LOG2E_F); p.w = ex2f_(f.w * LOG2E_F);
                reinterpret_cast<float4*>(dst)[q] = p;
            }
        }
        const int t2 = (2 < T) ? 2 : (T - 1);
        const int t3 = (3 < T) ? 3 : (T - 1);
        const float4* s2 = reinterpret_cast<const float4*>(obs_p + (size_t)t2 * S + sj_p);
        const float4* s3 = reinterpret_cast<const float4*>(obs_p + (size_t)t3 * S + sj_p);
#pragma unroll
        for (int q = 0; q < 4; ++q) {
            const float4 a = s2[q], c = s3[q];
            rng0[4 * q] = a.x; rng0[4 * q + 1] = a.y; rng0[4 * q + 2] = a.z; rng0[4 * q + 3] = a.w;
            rng1[4 * q] = c.x; rng1[4 * q + 1] = c.y; rng1[4 * q + 2] = c.z; rng1[4 * q + 3] = c.w;
        }
    }
    __syncthreads();

#define CRF_STEP(T_CUR, RNG)                                                      \
    {                                                                              \
        const int t_ = (T_CUR);                                                    \
        const int cb_ = (t_ - 1) & 1, nb_ = t_ & 1;                                \
        if (consumer) {                                                            \
            const bool fold_ = (t_ & 7) == 1;                                      \
            /* observation factors, ready since last barrier */                    \
            float2 pg_[2], pg8_[2];                                                \
            _Pragma("unroll")                                                      \
            for (int nn = 0; nn < 2; ++nn) {                                       \
                const int j0 = w * 16 + nn * 8 + 2 * tg;                           \
                pg_[nn]  = *reinterpret_cast<const float2*>(&Psm[nb_][ g      * PR + j0]); \
                pg8_[nn] = *reinterpret_cast<const float2*>(&Psm[nb_][(g + 8) * PR + j0]); \
            }                                                                      \
            if (fold_) {                                                           \
                const int eg  = (Vsm[cb_][ g      * VR] >> 7) & 0xFF;              \
                const int eg8 = (Vsm[cb_][(g + 8) * VR] >> 7) & 0xFF;              \
                const float scg  = __int_as_float((254 - eg ) << 23);              \
                const float scg8 = __int_as_float((254 - eg8) << 23);              \
                _Pragma("unroll")                                                  \
                for (int nn = 0; nn < 2; ++nn) {                                   \
                    pg_[nn].x *= scg;  pg_[nn].y *= scg;                           \
                    pg8_[nn].x *= scg8; pg8_[nn].y *= scg8;                        \
                }                                                                  \
                if (w == 0 && tg == 0) { Lacc[g] += eg - 127; Lacc[g + 8] += eg8 - 127; } \
            }                                                                      \
            /* two depth-4 accumulator chains per nn */                            \
            float cA_[2][4], cB_[2][4];                                            \
            _Pragma("unroll")                                                      \
            for (int nn = 0; nn < 2; ++nn)                                         \
                _Pragma("unroll")                                                  \
                for (int r = 0; r < 4; ++r) { cA_[nn][r] = 0.f; cB_[nn][r] = 0.f; }\
            _Pragma("unroll")                                                      \
            for (int kk = 0; kk < 4; ++kk) {                                       \
                unsigned a0, a1, a2, a3, e0, e1, e2, e3;                           \
                ldsm4_(a0, a1, a2, a3, vbase[cb_] + kk * 32);                      \
                ldsm4_(e0, e1, e2, e3, vbase[cb_] + (kk + 4) * 32);                \
                mma_bf16_(cA_[0], a0, a1, a2, a3, bh0[kk][0], bh1[kk][0]);         \
                mma_bf16_(cB_[0], e0, e1, e2, e3, bh0[kk + 4][0], bh1[kk + 4][0]); \
                mma_bf16_(cA_[1], a0, a1, a2, a3, bh0[kk][1], bh1[kk][1]);         \
                mma_bf16_(cB_[1], e0, e1, e2, e3, bh0[kk + 4][1], bh1[kk + 4][1]); \
            }                                                                      \
            _Pragma("unroll")                                                      \
            for (int nn = 0; nn < 2; ++nn) {                                       \
                const int j0 = w * 16 + nn * 8 + 2 * tg;                           \
                const float f0 = (cA_[nn][0] + cB_[nn][0]) * pg_[nn].x;            \
                const float f1 = (cA_[nn][1] + cB_[nn][1]) * pg_[nn].y;            \
                const float f2 = (cA_[nn][2] + cB_[nn][2]) * pg8_[nn].x;           \
                const float f3 = (cA_[nn][3] + cB_[nn][3]) * pg8_[nn].y;           \
                *reinterpret_cast<unsigned*>(&Vsm[nb_][ g      * VR + j0]) = pkf2_(f0, f1); \
                *reinterpret_cast<unsigned*>(&Vsm[nb_][(g + 8) * VR + j0]) = pkf2_(f2, f3); \
            }                                                                      \
        } else {                                                                   \
            /* producers: stage p(t+1); refill ring with obs[t+3] */               \
            if (t_ + 1 < T) {                                                      \
                float* dst = &Psm[(t_ + 1) & 1][sb_p * PR + sj_p];                 \
                _Pragma("unroll")                                                  \
                for (int q = 0; q < 4; ++q) {                                      \
                    float4 p;                                                      \
                    p.x = ex2f_((RNG)[4 * q + 0] * LOG2E_F);                       \
                    p.y = ex2f_((RNG)[4 * q + 1] * LOG2E_F);                       \
                    p.z = ex2f_((RNG)[4 * q + 2] * LOG2E_F);                       \
                    p.w = ex2f_((RNG)[4 * q + 3] * LOG2E_F);                       \
                    reinterpret_cast<float4*>(dst)[q] = p;                         \
                }                                                                  \
            }                                                                      \
            if (t_ + 3 < T) {                                                      \
                const float4* src = reinterpret_cast<const float4*>(obs_p + (size_t)(t_ + 3) * S + sj_p); \
                _Pragma("unroll")                                                  \
                for (int q = 0; q < 4; ++q) {                                      \
                    const float4 f = src[q];                                       \
                    (RNG)[4 * q + 0] = f.x; (RNG)[4 * q + 1] = f.y;                \
                    (RNG)[4 * q + 2] = f.z; (RNG)[4 * q + 3] = f.w;                \
                }                                                                  \
            }                                                                      \
        }                                                                          \
        __syncthreads();                                                           \
    }

    int t = 1;
    for (; t + 1 < T; t += 2) {
        CRF_STEP(t,     rng0)
        CRF_STEP(t + 1, rng1)
    }
    if (t < T) CRF_STEP(t, rng0)
#undef CRF_STEP

    // ---- finalize: out[b] = -ln2 * (log2(sum_j v[b][j]) + L[b]) ----
    const int fb = (T - 1) & 1;
    if (consumer) {
        float s8 = 0.f;
#pragma unroll
        for (int m = 0; m < 8; ++m)
            s8 += __bfloat162float(
                *reinterpret_cast<const __nv_bfloat16*>(&Vsm[fb][sb_c * VR + sj_c + m]));
        psum[sb_c][tid & 15] = s8;
    }
    __syncthreads();
    if (tid < SB && b0 + tid < B) {
        float s = 0.f;
#pragma unroll
        for (int k = 0; k < 16; ++k) s += psum[tid][k];
        out[b0 + tid] = -LN2_F * (lg2f_(s) + (float)Lacc[tid]);
    }
}

extern "C" void kernel_launch(void* const* d_in, const int* in_sizes, int n_in,
                              void* d_out, int out_size)
{
    const float* obs  = (const float*)d_in[0];   // [B, T, S] f32
    const float* logA = (const float*)d_in[1];   // [S, S]   f32
    float* out = (float*)d_out;                  // [B]      f32

    const int B = out_size;
    const int S = 128;
    const int T = in_sizes[0] / (B * S);

    const int grid = (B + 15) / 16;
    crf_mma_kernel<<<grid, 384>>>(obs, logA, out, T, B);
}